// round 6
// baseline (speedup 1.0000x reference)
#include <cuda_runtime.h>
#include <cstdint>
#include <cstddef>

// Problem constants
#define NB 32
#define NT 512
#define NI 256
#define NH 512

// -------------------- device scratch (no allocations allowed) --------------------
// xp layout: [d][t][row(2048)][b(32)], row = unit*4 + gate  (gate: 0=i,1=f,2=g,3=o)
__device__ float    g_xp[2u * 512u * 2048u * 32u];   // 268 MB
// h double buffer per direction: [d][buf][k(512)][b(32)]
__device__ float    g_h[2 * 2 * 512 * 32];
__device__ unsigned g_bar2[64];                      // per-direction counters, 128B apart

// -------------------- f32x2 helpers --------------------
__device__ __forceinline__ unsigned long long pk2(float a, float b) {
    unsigned long long r;
    asm("mov.b64 %0, {%1,%2};" : "=l"(r) : "f"(a), "f"(b));
    return r;
}
__device__ __forceinline__ void upk2(unsigned long long v, float& a, float& b) {
    asm("mov.b64 {%0,%1}, %2;" : "=f"(a), "=f"(b) : "l"(v));
}
__device__ __forceinline__ void fma2(unsigned long long& d, unsigned long long a, unsigned long long b) {
    asm("fma.rn.f32x2 %0, %1, %2, %0;" : "+l"(d) : "l"(a), "l"(b));
}
__device__ __forceinline__ void add2(unsigned long long& d, unsigned long long a) {
    asm("add.rn.f32x2 %0, %0, %1;" : "+l"(d) : "l"(a));
}

__device__ __forceinline__ float sigmoidf_(float x) {
    return 1.0f / (1.0f + __expf(-x));
}
__device__ __forceinline__ float tanh_fast(float x) {
    float r;
    asm("tanh.approx.f32 %0, %1;" : "=f"(r) : "f"(x));
    return r;
}

// ==================================================================================
// Phase A: input projections (init fused into first 8 blocks).
// xp[d][t][row][b] = sum_i x[b][t][i]*W_ih[d][wrow][i] + bias
// where row = unit*4+gate and wrow = gate*512 + unit.
// Block: (t-chunk of 32) x (64 rows) x (direction).  256 threads, 8 warps.
// ==================================================================================
#define XPROJ_SMEM (65536 + 64 * 33 * 16)  // 64KB packed weights + padded x tile

__global__ __launch_bounds__(256, 2) void k_xproj(
    const float* __restrict__ x,
    const float* __restrict__ Wf, const float* __restrict__ bf,
    const float* __restrict__ Wb, const float* __restrict__ bb)
{
    extern __shared__ char smem[];
    unsigned long long* sW = (unsigned long long*)smem;        // [256][32] u64 pairs (64KB)
    float*              fW = (float*)smem;                     // alias: fW[k*64 + lr]
    float4*             sX = (float4*)(smem + 65536);          // [k4(64)*33 + b] padded

    const int d    = blockIdx.z;
    const float* W    = d ? Wb : Wf;
    const float* bias = d ? bb : bf;
    const int R0   = blockIdx.y * 64;
    const int t0   = blockIdx.x * 32;
    const int tid  = threadIdx.x;
    const int lane = tid & 31;
    const int w    = tid >> 5;

    // ---- fused init: zero h buffer 0 of both directions + reset barrier counters
    if (blockIdx.z == 0 && blockIdx.y == 0 && blockIdx.x < 8) {
        int t = blockIdx.x * 256 + tid;   // 2048 threads
        #pragma unroll
        for (int i = 0; i < 8; i++) {
            g_h[t + i * 2048]         = 0.0f;   // dir 0, buf 0 (16384 floats)
            g_h[32768 + t + i * 2048] = 0.0f;   // dir 1, buf 0
        }
        if (t < 2) g_bar2[t * 32] = 0u;
    }

    // ---- load + pack weight slice: fW[k*64 + lr] = W[wrow(R0+lr)][k]
    {
        int lr   = tid & 63;
        int kb   = (tid >> 6) * 64;
        int grow = R0 + lr;
        int wrow = ((grow & 3) << 9) + (grow >> 2);
        const float* src = W + wrow * 256 + kb;
        #pragma unroll 8
        for (int k = 0; k < 64; k++)
            fW[(kb + k) * 64 + lr] = src[k];
    }

    // ---- per-thread bias values for its 8 rows
    float bv[8];
    #pragma unroll
    for (int r = 0; r < 8; r++) {
        int grow = R0 + w * 8 + r;
        bv[r] = bias[((grow & 3) << 9) + (grow >> 2)];
    }
    __syncthreads();

    for (int tl = 0; tl < 32; tl++) {
        int t = t0 + tl;
        __syncthreads();  // previous tile fully consumed
        // ---- load x tile: sX[k4*33 + b] = x[b][t][k4*4 .. +3]
        #pragma unroll
        for (int bi = 0; bi < 4; bi++) {
            int b = w + bi * 8;
            #pragma unroll
            for (int kh = 0; kh < 2; kh++) {
                int k4 = kh * 32 + lane;
                float4 v = *(const float4*)(x + ((size_t)(b * 512 + t)) * 256 + k4 * 4);
                sX[k4 * 33 + b] = v;
            }
        }
        __syncthreads();

        unsigned long long acc0 = 0, acc1 = 0, acc2 = 0, acc3 = 0;
        const unsigned long long* wbase = sW + w * 4;
        #pragma unroll 4
        for (int k4 = 0; k4 < 64; k4++) {
            float4 xv = sX[k4 * 33 + lane];
            #pragma unroll
            for (int kk = 0; kk < 4; kk++) {
                float xs = (&xv.x)[kk];
                unsigned long long hh = pk2(xs, xs);
                const unsigned long long* wp = wbase + (k4 * 4 + kk) * 32;
                ulonglong2 wa = *(const ulonglong2*)(wp);
                ulonglong2 wc = *(const ulonglong2*)(wp + 2);
                fma2(acc0, hh, wa.x);
                fma2(acc1, hh, wa.y);
                fma2(acc2, hh, wc.x);
                fma2(acc3, hh, wc.y);
            }
        }

        // ---- store 8 rows (coalesced over lanes = batch)
        float* outp = g_xp + ((((size_t)d * 512 + t) * 2048) + R0) * 32 + lane;
        float f0, f1;
        upk2(acc0, f0, f1);
        outp[(w * 8 + 0) * 32] = f0 + bv[0];
        outp[(w * 8 + 1) * 32] = f1 + bv[1];
        upk2(acc1, f0, f1);
        outp[(w * 8 + 2) * 32] = f0 + bv[2];
        outp[(w * 8 + 3) * 32] = f1 + bv[3];
        upk2(acc2, f0, f1);
        outp[(w * 8 + 4) * 32] = f0 + bv[4];
        outp[(w * 8 + 5) * 32] = f1 + bv[5];
        upk2(acc3, f0, f1);
        outp[(w * 8 + 6) * 32] = f0 + bv[6];
        outp[(w * 8 + 7) * 32] = f1 + bv[7];
    }
}

// ==================================================================================
// Phase B: persistent recurrent kernel (v4: crossbar-efficient operand tiling).
// 128 blocks, ~98KB smem, 1 block/SM, all co-resident, per-direction barriers safe.
// Block bid: d = bid>>6, owns hidden units j0 = (bid&63)*8 .. +8 of that direction.
// Compute: warp w covers k in [64w, 64w+64).
//   lane = (a = lane>>2, c = lane&3)
//   a selects gate-pair-weight indices {a, a+8} of 16  (wp = j*2+gp; gp0=(i,f), gp1=(g,o))
//     -> weights via 2 lane-distinct LDS.64 per k (1 crossbar phase each, no broadcast waste)
//   c selects batches {4c..4c+3} u {16+4c..16+4c+3}
//     -> h via 2 LDG.128 per k (1 L1tex wavefront each); (h,h) pairs made by register pk2
//   16 fma2 per k per lane; acc[s(2)][hb(2)][e(4)] = gate-pair of unit j=(a+8s)>>1 for
//   batch b = hb*16+4c+e.
// Cross-warp reduce via smem red[ww][wp][b] (stride 33 padding).
// Finalize: warp = unit j0+w, lane = batch; c stays in a register.
// ==================================================================================
#define RED_U64   ((8 * 16) * 33 + 33)
#define RECUR_SMEM (65536 + RED_U64 * 8)   // 64KB weight pairs + ~34KB reduce staging

__global__ __launch_bounds__(256, 1) void k_recur(
    const float* __restrict__ Whf,
    const float* __restrict__ Whb,
    float* __restrict__ out)
{
    extern __shared__ char smem[];
    unsigned long long* wS  = (unsigned long long*)smem;            // [512][16] u64, 64KB
    unsigned long long* red = (unsigned long long*)(smem + 65536);  // [8][16][33] u64

    const int bid  = blockIdx.x;
    const int d    = bid >> 6;
    const int j0   = (bid & 63) * 8;
    const int tid  = threadIdx.x;
    const int lane = tid & 31;
    const int w    = tid >> 5;
    const float* Wh = d ? Whb : Whf;

    // ---- load + pack W_hh slice: wS[k*16 + j*2+gp] = (w_i,w_f) / (w_g,w_o) for unit j0+j
    for (int idx = tid; idx < 512 * 8; idx += 256) {
        int k  = idx >> 3;
        int j  = idx & 7;
        int jg = j0 + j;
        float wi = Wh[((0 * 512) + jg) * 512 + k];
        float wf = Wh[((1 * 512) + jg) * 512 + k];
        float wg = Wh[((2 * 512) + jg) * 512 + k];
        float wo = Wh[((3 * 512) + jg) * 512 + k];
        wS[k * 16 + j * 2 + 0] = pk2(wi, wf);
        wS[k * 16 + j * 2 + 1] = pk2(wg, wo);
    }
    __syncthreads();

    const int a = lane >> 2;                    // 0..7  weight-pair group
    const int c = lane & 3;                     // 0..3  batch group
    const int jg_fin = j0 + w;                  // finalize: unit = warp id, batch = lane
    float* hbufs = g_h + d * 2 * 512 * 32;
    volatile unsigned* barp = &g_bar2[d * 32];
    float  cst = 0.0f;
    const int kbase = w * 64;

    // prefetch xp for step 0
    float xp_i, xp_f, xp_g, xp_o;
    {
        const int tt0 = d ? 511 : 0;
        const float* xpp = g_xp + (((size_t)d * 512 + tt0) * 2048 + (size_t)jg_fin * 4) * 32 + lane;
        xp_i = xpp[0]; xp_f = xpp[32]; xp_g = xpp[64]; xp_o = xpp[96];
    }

    for (int s = 0; s < 512; s++) {
        const int tt = d ? (511 - s) : s;

        const float* hsrc = hbufs + (s & 1) * 16384;
        const float4* h0p = (const float4*)(hsrc + 4 * c);        // + k*8 float4
        const float4* h1p = (const float4*)(hsrc + 16 + 4 * c);

        unsigned long long acc[2][2][4];
        #pragma unroll
        for (int s2 = 0; s2 < 2; s2++)
            #pragma unroll
            for (int hb = 0; hb < 2; hb++)
                #pragma unroll
                for (int e = 0; e < 4; e++) acc[s2][hb][e] = 0ull;

        #pragma unroll 4
        for (int kl = 0; kl < 64; kl++) {
            const int k = kbase + kl;
            float4 fa = h0p[k * 8];
            float4 fb = h1p[k * 8];
            unsigned long long w0 = wS[k * 16 + a];
            unsigned long long w1 = wS[k * 16 + a + 8];
            #pragma unroll
            for (int e = 0; e < 4; e++) {
                unsigned long long ha = pk2((&fa.x)[e], (&fa.x)[e]);
                unsigned long long hb2 = pk2((&fb.x)[e], (&fb.x)[e]);
                fma2(acc[0][0][e], w0, ha);
                fma2(acc[1][0][e], w1, ha);
                fma2(acc[0][1][e], w0, hb2);
                fma2(acc[1][1][e], w1, hb2);
            }
        }

        // ---- stage partials: red[w][wp][b], wp = a+8*s2, b = hb*16+4c+e
        #pragma unroll
        for (int s2 = 0; s2 < 2; s2++) {
            int wp = a + 8 * s2;
            #pragma unroll
            for (int hb = 0; hb < 2; hb++)
                #pragma unroll
                for (int e = 0; e < 4; e++)
                    red[(w * 16 + wp) * 33 + hb * 16 + 4 * c + e] = acc[s2][hb][e];
        }
        __syncthreads();

        // ---- finalize: warp w = unit j0+w, lane = batch
        unsigned long long s0 = 0ull, s1 = 0ull;
        #pragma unroll
        for (int ww = 0; ww < 8; ww++) {
            add2(s0, red[(ww * 16 + 2 * w + 0) * 33 + lane]);
            add2(s1, red[(ww * 16 + 2 * w + 1) * 33 + lane]);
        }
        float gi, gf, gg, go;
        upk2(s0, gi, gf);
        upk2(s1, gg, go);

        gi += xp_i; gf += xp_f; gg += xp_g; go += xp_o;
        gi = sigmoidf_(gi);
        gf = sigmoidf_(gf);
        go = sigmoidf_(go);
        gg = tanh_fast(gg);
        cst = gf * cst + gi * gg;
        float h = go * tanh_fast(cst);

        // h -> next buffer (coalesced: [k][b]); output (write-through)
        hbufs[((s + 1) & 1) * 16384 + jg_fin * 32 + lane] = h;
        out[((size_t)lane * 512 + tt) * 1024 + d * 512 + jg_fin] = h;

        // ---- prefetch xp for step s+1 (DRAM latency overlaps the barrier spin)
        if (s + 1 < 512) {
            const int ttn = d ? (510 - s) : (s + 1);
            const float* xpp = g_xp + (((size_t)d * 512 + ttn) * 2048 + (size_t)jg_fin * 4) * 32 + lane;
            xp_i = xpp[0]; xp_f = xpp[32]; xp_g = xpp[64]; xp_o = xpp[96];
        }

        // ---- per-direction barrier (64 blocks each, all 128 CTAs resident)
        __syncthreads();
        if (tid == 0) {
            __threadfence();
            atomicAdd((unsigned*)barp, 1u);
            unsigned target = (unsigned)(s + 1) * 64u;
            while (*barp < target) { }
            __threadfence();
        }
        __syncthreads();
    }
}

// ==================================================================================
extern "C" void kernel_launch(void* const* d_in, const int* in_sizes, int n_in,
                              void* d_out, int out_size)
{
    const float* x    = (const float*)d_in[0];
    const float* Wihf = (const float*)d_in[1];
    const float* Whhf = (const float*)d_in[2];
    const float* bf   = (const float*)d_in[3];
    const float* Wihb = (const float*)d_in[4];
    const float* Whhb = (const float*)d_in[5];
    const float* bb   = (const float*)d_in[6];
    float* out = (float*)d_out;

    cudaFuncSetAttribute(k_xproj, cudaFuncAttributeMaxDynamicSharedMemorySize, XPROJ_SMEM);
    cudaFuncSetAttribute(k_recur, cudaFuncAttributeMaxDynamicSharedMemorySize, RECUR_SMEM);

    k_xproj<<<dim3(16, 32, 2), 256, XPROJ_SMEM>>>(x, Wihf, bf, Wihb, bb);
    k_recur<<<128, 256, RECUR_SMEM>>>(Whhf, Whhb, out);
}